// round 1
// baseline (speedup 1.0000x reference)
#include <cuda_runtime.h>

// Problem constants (fixed by the reference):
//   orig_fea [256, 300, 256] f32; ind0/ind1 [32,32,4] i32; W1a/W1b [256,256];
//   b1[256]; W2[256,1]; b2[1]. L = num_top*cobj = 128, pool = 1200.
#define LN   128   // L
#define DD   256   // feature dim
#define HH   256   // hidden
#define NUMG 32    // num
#define BAG  300

// Scratch: h0/h1 stored transposed: [side][n][h][a]  (8 MB)
__device__ float g_hT[2][NUMG][HH][LN];

// ---------------------------------------------------------------------------
// Kernel 1: gather rows of orig_fea per (side, n), GEMM with W1a/W1b,
// write transposed (+b1 folded into side 0).
// grid: (H/64=4, L/64=2, 64 = side*32+n), block 256.
// ---------------------------------------------------------------------------
__global__ __launch_bounds__(256)
void gemm_gather_kernel(const float* __restrict__ orig,
                        const int*   __restrict__ ind0,
                        const int*   __restrict__ ind1,
                        const float* __restrict__ W1a,
                        const float* __restrict__ W1b,
                        const float* __restrict__ b1)
{
    const int side = blockIdx.z >> 5;
    const int n    = blockIdx.z & 31;
    const int m0   = blockIdx.y * 64;   // a-tile
    const int h0   = blockIdx.x * 64;   // h-tile
    const int*   __restrict__ ind = side ? ind1 : ind0;
    const float* __restrict__ W   = side ? W1b  : W1a;

    __shared__ float As[16][68];   // [k][m], padded
    __shared__ float Bs[16][64];   // [k][h]
    __shared__ int   rowoff[64];

    const int t = threadIdx.x;
    if (t < 64) {
        int a = m0 + t;
        int p = ind[n * LN + a] + BAG * (a & 3);          // pool index [0,1200)
        rowoff[t] = ((n * 2 + side) * 1200 + p) * DD;     // float offset into orig
    }
    __syncthreads();

    float acc[4][4];
#pragma unroll
    for (int j = 0; j < 4; j++)
#pragma unroll
        for (int i = 0; i < 4; i++) acc[j][i] = 0.f;

    const int lm = t >> 2, lq = t & 3;    // A-load mapping
    const int bk = t >> 4, bq = t & 15;   // B-load mapping
    const int ty = t >> 4, tx = t & 15;   // compute mapping

    for (int k0 = 0; k0 < DD; k0 += 16) {
        float4 av = *(const float4*)(orig + rowoff[lm] + k0 + lq * 4);
        float4 bv = *(const float4*)(W + (k0 + bk) * HH + h0 + bq * 4);
        As[lq * 4 + 0][lm] = av.x;
        As[lq * 4 + 1][lm] = av.y;
        As[lq * 4 + 2][lm] = av.z;
        As[lq * 4 + 3][lm] = av.w;
        *(float4*)&Bs[bk][bq * 4] = bv;
        __syncthreads();
#pragma unroll
        for (int kk = 0; kk < 16; kk++) {
            float4 a4 = *(const float4*)&As[kk][ty * 4];
            float4 b4 = *(const float4*)&Bs[kk][tx * 4];
            float aa[4] = {a4.x, a4.y, a4.z, a4.w};
            float bb[4] = {b4.x, b4.y, b4.z, b4.w};
#pragma unroll
            for (int j = 0; j < 4; j++)
#pragma unroll
                for (int i = 0; i < 4; i++)
                    acc[j][i] = fmaf(aa[j], bb[i], acc[j][i]);
        }
        __syncthreads();
    }

    // epilogue: +b1 (side 0 only), write transposed [h][a]
    float bias[4] = {0.f, 0.f, 0.f, 0.f};
    if (side == 0) {
        float4 bv = *(const float4*)&b1[h0 + tx * 4];
        bias[0] = bv.x; bias[1] = bv.y; bias[2] = bv.z; bias[3] = bv.w;
    }
#pragma unroll
    for (int i = 0; i < 4; i++) {
        float4 v;
        v.x = acc[0][i] + bias[i];
        v.y = acc[1][i] + bias[i];
        v.z = acc[2][i] + bias[i];
        v.w = acc[3][i] + bias[i];
        *(float4*)&g_hT[side][n][h0 + tx * 4 + i][m0 + ty * 4] = v;
    }
}

// ---------------------------------------------------------------------------
// Kernel 2: scores[n,m,l] = sum_{pa,pb<4, h} relu(h0[n,a,h]+h1[n,b,h])*W2[h]
//           (+16*b2), with a = m*4+pa, b = l*4+pb.
// grid: 128 = 32 n * 4 a-tiles; block 256 (ty 0..7 -> 4 a's, tx 0..31 -> 4 b's)
// Each thread's 4x4 register tile == exactly one 4x4 patch -> one output.
// ---------------------------------------------------------------------------
__global__ __launch_bounds__(256)
void pairwise_kernel(const float* __restrict__ W2,
                     const float* __restrict__ b2,
                     float* __restrict__ out)
{
    const int n  = blockIdx.x >> 2;
    const int at = blockIdx.x & 3;
    const int a0 = at * 32;
    const int t  = threadIdx.x;
    const int ty = t >> 5;   // 0..7
    const int tx = t & 31;   // 0..31

    __shared__ float xs[32][32];    // [h][a_local]
    __shared__ float ys[32][128];   // [h][b]
    __shared__ float ws[32];

    float acc[4][4];
#pragma unroll
    for (int j = 0; j < 4; j++)
#pragma unroll
        for (int i = 0; i < 4; i++) acc[j][i] = 0.f;

    for (int h0 = 0; h0 < HH; h0 += 32) {
        {
            int hh = t >> 3, q = t & 7;
            *(float4*)&xs[hh][q * 4] =
                *(const float4*)&g_hT[0][n][h0 + hh][a0 + q * 4];
        }
#pragma unroll
        for (int r = 0; r < 4; r++) {
            int id = t + 256 * r;
            int hh = id >> 5, q = id & 31;
            *(float4*)&ys[hh][q * 4] =
                *(const float4*)&g_hT[1][n][h0 + hh][q * 4];
        }
        if (t < 32) ws[t] = W2[h0 + t];   // W2 is [H,1]
        __syncthreads();

#pragma unroll 8
        for (int hh = 0; hh < 32; hh++) {
            float w = ws[hh];
            float4 xv = *(const float4*)&xs[hh][ty * 4];
            float4 yv = *(const float4*)&ys[hh][tx * 4];
            float xa[4] = {xv.x, xv.y, xv.z, xv.w};
            float yb[4] = {yv.x, yv.y, yv.z, yv.w};
#pragma unroll
            for (int j = 0; j < 4; j++)
#pragma unroll
                for (int i = 0; i < 4; i++)
                    acc[j][i] = fmaf(fmaxf(xa[j] + yb[i], 0.f), w, acc[j][i]);
        }
        __syncthreads();
    }

    float s = 0.f;
#pragma unroll
    for (int j = 0; j < 4; j++)
#pragma unroll
        for (int i = 0; i < 4; i++) s += acc[j][i];
    s += 16.f * b2[0];

    const int m = at * 8 + ty;     // patch row
    const int l = tx;              // patch col
    out[n * 1024 + m * 32 + l] = s;
}

// ---------------------------------------------------------------------------
// Kernel 3: pairs = meshgrid(ij) values, as floats, appended after scores.
// pairs[n][idx][0] = idx/32, pairs[n][idx][1] = idx%32
// ---------------------------------------------------------------------------
__global__ __launch_bounds__(256)
void pairs_kernel(float* __restrict__ outp)
{
    int id = blockIdx.x * 256 + threadIdx.x;   // < 65536
    int pi    = id >> 1;
    int which = id & 1;
    int idx   = pi & 1023;
    int v = which ? (idx & 31) : (idx >> 5);
    outp[id] = (float)v;
}

extern "C" void kernel_launch(void* const* d_in, const int* in_sizes, int n_in,
                              void* d_out, int out_size)
{
    const float* orig = (const float*)d_in[0];
    const int*   ind0 = (const int*)d_in[1];
    const int*   ind1 = (const int*)d_in[2];
    // If the scalar k is materialized as an input it sits at index 3 (size 1).
    int i = 3;
    if (n_in >= 9 && in_sizes[3] == 1) i = 4;
    const float* W1a = (const float*)d_in[i + 0];
    const float* W1b = (const float*)d_in[i + 1];
    const float* b1  = (const float*)d_in[i + 2];
    const float* W2  = (const float*)d_in[i + 3];
    const float* b2  = (const float*)d_in[i + 4];
    float* out = (float*)d_out;

    dim3 g1(HH / 64, LN / 64, 2 * NUMG);   // (4, 2, 64)
    gemm_gather_kernel<<<g1, 256>>>(orig, ind0, ind1, W1a, W1b, b1);
    pairwise_kernel<<<NUMG * 4, 256>>>(W2, b2, out);

    const int scores_elems = NUMG * 1024;          // 32768
    const int pairs_elems  = NUMG * 1024 * 2;      // 65536
    if (out_size >= scores_elems + pairs_elems)
        pairs_kernel<<<pairs_elems / 256, 256>>>(out + scores_elems);
}